// round 6
// baseline (speedup 1.0000x reference)
#include <cuda_runtime.h>
#include <math.h>

#define DN   128
#define HK   65
#define BN   4
#define TN   2
#define GN   125
#define PERB (TN*GN)      // 250
#define NBTG (BN*PERB)    // 1000
#define WIN  24
#define H0   52
#define KT   9            // ceil(65/8) kx tiles
#define CP   130          // padded column stride for tile kernels

// ---------------- scratch (static device memory; no allocation) ----------------
__device__ float2 g_vf[DN*DN*HK];     // vol rfft, z/y fftshifted, x natural (8.5 MB)
__device__ float2 g_fimg[BN*DN*HK];   // image rffts, y fftshifted
__device__ float2 g_tw[128];          // exp(-2*pi*i*j/128)
__device__ float  g_corr[NBTG];
__device__ int    g_argm[NBTG];

__device__ __forceinline__ float2 cmulf(float2 a, float2 b){
    return make_float2(a.x*b.x - a.y*b.y, a.x*b.y + a.y*b.x);
}

// ---------------- one-time twiddle table ----------------
__global__ void kInit(){
    int j = threadIdx.x;
    float s, c;
    sincosf(-6.283185307179586f * (float)j * (1.0f/128.0f), &s, &c);
    g_tw[j] = make_float2(c, s);
}

// ---------------- warp-local 128-pt FFT: one warp, 2 butterflies/thread ------
__device__ __forceinline__ void fft128_w32(float2* col, const float2* Ef, int lane){
    for (int shift = 6; shift >= 0; shift--){
        int half = 1 << shift;
        int twsh = 6 - shift;               // Ef stride = 1 << twsh
        #pragma unroll
        for (int k = 0; k < 2; k++){
            int bf   = lane + k*32;         // 0..63
            int j    = bf & (half - 1);
            int grp  = bf >> shift;
            int base = (grp << (shift + 1)) + j;
            float2 u = col[base];
            float2 v = col[base + half];
            float2 d = make_float2(u.x - v.x, u.y - v.y);
            col[base]        = make_float2(u.x + v.x, u.y + v.y);
            col[base + half] = cmulf(d, Ef[j << twsh]);
        }
        __syncwarp();
    }
    float2 r[4];
    #pragma unroll
    for (int k = 0; k < 4; k++) r[k] = col[lane + k*32];
    __syncwarp();
    #pragma unroll
    for (int k = 0; k < 4; k++){
        int y = lane + k*32;
        col[(int)(__brev((unsigned)y) >> 25)] = r[k];
    }
    __syncwarp();
}

// ---------------- volume pass X: warp-per-row rfft, sinc^2 weight ------------
__global__ void __launch_bounds__(256) kVolXW(const float* __restrict__ vol){
    __shared__ float2 ws[8][128];
    __shared__ float2 Ef[128];
    int tid = threadIdx.x, wid = tid >> 5, lane = tid & 31;
    if (tid < 128) Ef[tid] = g_tw[tid];
    __syncthreads();
    int row = blockIdx.x * 8 + wid;       // 0..16383
    int z = row >> 7, y = row & 127;
    float fz = (float)(z - 64) * (1.0f/128.0f);
    float fy = (float)(y - 64) * (1.0f/128.0f);
    float fzy = fz*fz + fy*fy;
    float2* w = ws[wid];
    #pragma unroll
    for (int k = 0; k < 4; k++){
        int x = lane + k*32;
        float fx = (float)(x - 64) * (1.0f/128.0f);
        float r  = sqrtf(fzy + fx*fx);
        float wt;
        if (r < 1e-12f) wt = 1.0f;
        else { float pr = 3.14159265358979f * r; wt = __sinf(pr) / pr; }
        wt = wt * wt;
        w[(x + 64) & 127] = make_float2(vol[(z*DN + y)*DN + x] * wt, 0.0f);
    }
    __syncwarp();
    fft128_w32(w, Ef, lane);
    #pragma unroll
    for (int k = 0; k < 3; k++){
        int x = lane + k*32;
        if (x < HK) g_vf[(z*DN + y)*HK + x] = w[x];
    }
}

// Pass Y (tiled, padded): block = (z, 8-wide kx tile)
__global__ void __launch_bounds__(256) kVolYT(){
    __shared__ float2 a[8][CP];
    __shared__ float2 Ef[128];
    int tid = threadIdx.x;
    int z   = blockIdx.x / KT;
    int kt  = blockIdx.x % KT;
    int kx0 = kt * 8;
    if (tid < 128) Ef[tid] = g_tw[tid];
    #pragma unroll
    for (int k = 0; k < 4; k++){
        int idx = tid + k*256;
        int y = idx >> 3, c = idx & 7;
        int kx = kx0 + c;
        if (kx < HK){
            int ys = (y + 64) & 127;
            a[c][y] = g_vf[(z*DN + ys)*HK + kx];
        }
    }
    __syncthreads();
    int wid = tid >> 5, lane = tid & 31;
    if (kx0 + wid < HK) fft128_w32(a[wid], Ef, lane);
    __syncthreads();
    #pragma unroll
    for (int k = 0; k < 4; k++){
        int idx = tid + k*256;
        int y = idx >> 3, c = idx & 7;
        int kx = kx0 + c;
        if (kx < HK){
            int ys = (y + 64) & 127;
            g_vf[(z*DN + ys)*HK + kx] = a[c][y];
        }
    }
}

// Pass Z (tiled, padded): block = (sy, 8-wide kx tile)
__global__ void __launch_bounds__(256) kVolZT(){
    __shared__ float2 a[8][CP];
    __shared__ float2 Ef[128];
    int tid = threadIdx.x;
    int sy  = blockIdx.x / KT;
    int kt  = blockIdx.x % KT;
    int kx0 = kt * 8;
    if (tid < 128) Ef[tid] = g_tw[tid];
    #pragma unroll
    for (int k = 0; k < 4; k++){
        int idx = tid + k*256;
        int zz = idx >> 3, c = idx & 7;
        int kx = kx0 + c;
        if (kx < HK){
            int zs = (zz + 64) & 127;
            a[c][zz] = g_vf[(zs*DN + sy)*HK + kx];
        }
    }
    __syncthreads();
    int wid = tid >> 5, lane = tid & 31;
    if (kx0 + wid < HK) fft128_w32(a[wid], Ef, lane);
    __syncthreads();
    #pragma unroll
    for (int k = 0; k < 4; k++){
        int idx = tid + k*256;
        int zz = idx >> 3, c = idx & 7;
        int kx = kx0 + c;
        if (kx < HK){
            int zs = (zz + 64) & 127;
            g_vf[(zs*DN + sy)*HK + kx] = a[c][zz];
        }
    }
}

// ---------------- fused 2D image rfft: one block per image ----------------
// dynamic smem: buf[128][66] | ws[8][128] | Ef[128]
__global__ void __launch_bounds__(256) kImg2D(const float* __restrict__ imgs){
    extern __shared__ float2 dyn[];
    float2* buf = dyn;                   // row-major [128][66]
    float2* ws  = dyn + 128*66;          // [8][128]
    float2* Ef  = dyn + 128*66 + 8*128;
    int tid = threadIdx.x, wid = tid >> 5, lane = tid & 31;
    int b = blockIdx.x;
    if (tid < 128) Ef[tid] = g_tw[tid];
    __syncthreads();
    float2* w = ws + wid*128;
    // rows
    for (int it = 0; it < 16; it++){
        int r = it*8 + wid;
        #pragma unroll
        for (int k = 0; k < 4; k++){
            int x = lane + k*32;
            w[(x + 64) & 127] = make_float2(imgs[(b*DN + r)*DN + x], 0.0f);
        }
        __syncwarp();
        fft128_w32(w, Ef, lane);
        #pragma unroll
        for (int k = 0; k < 3; k++){
            int x = lane + k*32;
            if (x < HK) buf[r*66 + x] = w[x];
        }
        __syncwarp();
    }
    __syncthreads();
    // columns
    for (int it = 0; it < 9; it++){
        int kx = it*8 + wid;
        if (kx < HK){
            #pragma unroll
            for (int k = 0; k < 4; k++){
                int y = lane + k*32;
                int ys = (y + 64) & 127;
                w[y] = buf[ys*66 + kx];
            }
            __syncwarp();
            fft128_w32(w, Ef, lane);
            #pragma unroll
            for (int k = 0; k < 4; k++){
                int y = lane + k*32;
                int ys = (y + 64) & 127;
                g_fimg[(b*DN + ys)*HK + kx] = w[y];
            }
        }
    }
}

// ---------------- main matcher: one block per (b,t,g) ----------------
__global__ void __launch_bounds__(256) kMatch(const float* __restrict__ ctf,
                                              const float* __restrict__ rotm,
                                              const float* __restrict__ gridm){
    __shared__ float2 Pp[32][HK];     // product stripe (signs/alpha folded)
    __shared__ float2 G1[128][WIN];   // stage-1 result
    __shared__ float2 Ei[128];        // exp(+2*pi*i*j/128)
    __shared__ float  Ac[3], Bc[3];
    __shared__ float  rv[256];
    __shared__ int    ri[256];

    int tid = threadIdx.x;
    int bid = blockIdx.x;
    int b  = bid / PERB;
    int rr = bid % PERB;
    int t  = rr / GN;
    int g  = rr % GN;

    if (tid < 128){
        float2 tw = g_tw[tid];
        Ei[tid] = make_float2(tw.x, -tw.y);   // conj -> exp(+i...)
    }
    if (tid < 3){
        int i  = tid;
        int ii = 2 - i;
        const float* R  = rotm  + ((b*TN + t)*3 + ii)*3;
        const float* Gm = gridm + g*9;
        Ac[i] = R[0]*Gm[1] + R[1]*Gm[4] + R[2]*Gm[7];
        Bc[i] = R[0]*Gm[0] + R[1]*Gm[3] + R[2]*Gm[6];
    }
    __syncthreads();
    float A0=Ac[0], A1=Ac[1], A2=Ac[2], B0=Bc[0], B1=Bc[1], B2=Bc[2];

    const float*  ctfb = ctf    + b*DN*HK;
    const float2* fib  = g_fimg + b*DN*HK;

    int hh1  = tid & 31;        // stage-1 row for this thread
    int grp1 = tid >> 5;        // stage-1 column group (0..7), v = 3*grp1 + {0,1,2}
    int sb0  = H0 + 3*grp1;

    for (int stripe = 0; stripe < 4; stripe++){
        int hbase = stripe * 32;
        // ---- stage 0: slice extraction + product ----
        for (int idx = tid; idx < 32*HK; idx += 256){
            int hh = idx / HK;
            int l  = idx - hh*HK;
            int h  = hbase + hh;
            float hm = (float)(h - 64);
            float lf = (float)l;
            float v0 = A0*hm + B0*lf;
            float v1 = A1*hm + B1*lf;
            float v2 = A2*hm + B2*lf;
            bool neg = (v2 < 0.0f);
            if (neg){ v0 = -v0; v1 = -v1; v2 = -v2; }
            float zc = v0 + 64.0f, yc = v1 + 64.0f, xc = v2;
            float zf = floorf(zc), yf = floorf(yc), xf = floorf(xc);
            int z0 = (int)zf, y0 = (int)yf, x0 = (int)xf;
            float fz = zc - zf, fy = yc - yf, fx = xc - xf;
            float2 acc = make_float2(0.0f, 0.0f);
            #pragma unroll
            for (int dz = 0; dz < 2; dz++){
                int zi = z0 + dz;
                if (zi < 0 || zi >= DN) continue;
                float wz = dz ? fz : 1.0f - fz;
                #pragma unroll
                for (int dy = 0; dy < 2; dy++){
                    int yi = y0 + dy;
                    if (yi < 0 || yi >= DN) continue;
                    float wzy = wz * (dy ? fy : 1.0f - fy);
                    #pragma unroll
                    for (int dx = 0; dx < 2; dx++){
                        int xi = x0 + dx;
                        if (xi < 0 || xi >= HK) continue;
                        float ww = wzy * (dx ? fx : 1.0f - fx);
                        float2 vv = __ldg(&g_vf[(zi*DN + yi)*HK + xi]);
                        acc.x += vv.x * ww;
                        acc.y += vv.y * ww;
                    }
                }
            }
            if (neg) acc.y = -acc.y;                 // conj
            float  cf = __ldg(&ctfb[h*HK + l]);
            float2 fi = fib[h*HK + l];
            float px = cf * (fi.x*acc.x + fi.y*acc.y);
            float py = cf * (fi.y*acc.x - fi.x*acc.y);
            float sgn = ((h + l) & 1) ? -1.0f : 1.0f;
            if (l != 0 && l != 64) sgn *= 2.0f;      // Hermitian alpha weight
            Pp[hh][l] = make_float2(px*sgn, py*sgn);
        }
        __syncthreads();
        // ---- stage 1: contract 65 x-freqs -> 24 output columns ----
        {
            float2 a0 = make_float2(0.f,0.f), a1 = a0, a2 = a0;
            int i0 = 0, i1 = 0, i2 = 0;
            for (int l = 0; l < HK; l++){
                float2 p  = Pp[hh1][l];
                float2 w0 = Ei[i0];
                float2 w1 = Ei[i1];
                float2 w2 = Ei[i2];
                a0.x += p.x*w0.x - p.y*w0.y;  a0.y += p.x*w0.y + p.y*w0.x;
                a1.x += p.x*w1.x - p.y*w1.y;  a1.y += p.x*w1.y + p.y*w1.x;
                a2.x += p.x*w2.x - p.y*w2.y;  a2.y += p.x*w2.y + p.y*w2.x;
                i0 = (i0 + sb0    ) & 127;
                i1 = (i1 + sb0 + 1) & 127;
                i2 = (i2 + sb0 + 2) & 127;
            }
            int row = hbase + hh1, vb = 3*grp1;
            G1[row][vb+0] = a0;
            G1[row][vb+1] = a1;
            G1[row][vb+2] = a2;
        }
        __syncthreads();
    }
    // ---- stage 2: contract 128 rows -> 24 output rows, take Re ----
    float best = -3.4e38f;
    int bestIdx = 0x7fffffff;
    if (tid < 192){
        int v  = tid % 24;
        int ug = tid / 24;
        int ub0 = H0 + 3*ug;
        float r0 = 0.f, r1 = 0.f, r2 = 0.f;
        int i0 = 0, i1 = 0, i2 = 0;
        for (int h = 0; h < 128; h++){
            float2 gv = G1[h][v];
            float2 w0 = Ei[i0];
            float2 w1 = Ei[i1];
            float2 w2 = Ei[i2];
            r0 += gv.x*w0.x - gv.y*w0.y;
            r1 += gv.x*w1.x - gv.y*w1.y;
            r2 += gv.x*w2.x - gv.y*w2.y;
            i0 = (i0 + ub0    ) & 127;
            i1 = (i1 + ub0 + 1) & 127;
            i2 = (i2 + ub0 + 2) & 127;
        }
        #pragma unroll
        for (int j = 0; j < 3; j++){
            int u = 3*ug + j;
            float val = (j == 0 ? r0 : (j == 1 ? r1 : r2)) * (1.0f/16384.0f);
            if (u & 1) val = -val;                  // (-1)^(52+u)
            int idx = u*WIN + v;
            if (val > best || (val == best && idx < bestIdx)){ best = val; bestIdx = idx; }
        }
    }
    rv[tid] = best; ri[tid] = bestIdx;
    __syncthreads();
    for (int s = 128; s; s >>= 1){
        if (tid < s){
            float v2 = rv[tid+s]; int i2 = ri[tid+s];
            if (v2 > rv[tid] || (v2 == rv[tid] && i2 < ri[tid])){ rv[tid] = v2; ri[tid] = i2; }
        }
        __syncthreads();
    }
    if (tid == 0){ g_corr[bid] = rv[0]; g_argm[bid] = ri[0]; }
}

// ---------------- final per-batch reduction ----------------
__global__ void __launch_bounds__(256) kReduce(const float* __restrict__ gridm,
                                               float* __restrict__ out){
    __shared__ float sv[256];
    __shared__ int   si[256];
    __shared__ float s_mean, s_std;
    __shared__ float s_val[2];
    __shared__ int   s_idx[2];
    int b = blockIdx.x, tid = threadIdx.x;
    float v = (tid < PERB) ? g_corr[b*PERB + tid] : 0.0f;

    sv[tid] = (tid < PERB) ? v : 0.0f;
    __syncthreads();
    for (int s = 128; s; s >>= 1){ if (tid < s) sv[tid] += sv[tid+s]; __syncthreads(); }
    if (tid == 0) s_mean = sv[0] / (float)PERB;
    __syncthreads();
    float mean = s_mean;
    float d = (tid < PERB) ? (v - mean) : 0.0f;
    sv[tid] = d * d;
    __syncthreads();
    for (int s = 128; s; s >>= 1){ if (tid < s) sv[tid] += sv[tid+s]; __syncthreads(); }
    if (tid == 0) s_std = sqrtf(sv[0] / (float)(PERB - 1));
    __syncthreads();
    float stdv = s_std;

    for (int k = 0; k < 2; k++){
        bool excl = (k == 1 && tid == s_idx[0]);
        sv[tid] = (tid < PERB && !excl) ? v : -3.4e38f;
        si[tid] = tid;
        __syncthreads();
        for (int s = 128; s; s >>= 1){
            if (tid < s){
                float v2 = sv[tid+s]; int i2 = si[tid+s];
                if (v2 > sv[tid] || (v2 == sv[tid] && i2 < si[tid])){ sv[tid] = v2; si[tid] = i2; }
            }
            __syncthreads();
        }
        if (tid == 0){ s_val[k] = sv[0]; s_idx[k] = si[0]; }
        __syncthreads();
    }

    if (tid < 2){
        int k = tid;
        float val = s_val[k];
        int   idx = s_idx[k];
        int   gg  = idx % GN;
        int   a   = g_argm[b*PERB + idx];
        int   u   = a / WIN;
        int   vv  = a - u*WIN;
        int slot  = b*2 + k;
        out[slot] = val;
        for (int j = 0; j < 9; j++) out[8 + slot*9 + j] = gridm[gg*9 + j];
        out[80 + slot*2 + 0] = -((float)(H0 + vv) - 64.0f) * 1.5f;
        out[80 + slot*2 + 1] = -((float)(H0 + u)  - 64.0f) * 1.5f;
        float zz = (val - mean) / (stdv * 1.41421356237f);
        out[96 + slot] = 0.5f * (1.0f + erff(zz));
    }
}

// ---------------- launch ----------------
extern "C" void kernel_launch(void* const* d_in, const int* in_sizes, int n_in,
                              void* d_out, int out_size){
    const float* vol   = (const float*)d_in[0];
    const float* imgs  = (const float*)d_in[1];
    const float* ctf   = (const float*)d_in[2];
    const float* rotm  = (const float*)d_in[3];
    const float* gridm = (const float*)d_in[4];

    const int IMG_SMEM = (128*66 + 8*128 + 128) * (int)sizeof(float2);  // 76800 B
    cudaFuncSetAttribute(kImg2D, cudaFuncAttributeMaxDynamicSharedMemorySize, IMG_SMEM);

    kInit<<<1, 128>>>();                       // launch 1
    kVolXW<<<DN*DN/8, 256>>>(vol);             // launch 2
    kVolYT<<<DN*KT, 256>>>();                  // launch 3
    kVolZT<<<DN*KT, 256>>>();                  // launch 4
    kImg2D<<<BN, 256, IMG_SMEM>>>(imgs);       // launch 5
    kMatch<<<NBTG, 256>>>(ctf, rotm, gridm);   // launch 6  <- profiled by ncu -s 5 -c 1
    kReduce<<<BN, 256>>>(gridm, (float*)d_out);
}

// round 7
// speedup vs baseline: 1.2981x; 1.2981x over previous
#include <cuda_runtime.h>
#include <math.h>

#define DN   128
#define HK   65
#define BN   4
#define TN   2
#define GN   125
#define PERB (TN*GN)      // 250
#define NBTG (BN*PERB)    // 1000
#define WIN  24
#define H0   52
#define KT   9            // ceil(65/8) kx tiles
#define CP   130          // padded column stride for tile kernels

// ---------------- scratch (static device memory; no allocation) ----------------
__device__ float2 g_vf[DN*DN*HK];       // vol rfft, z/y fftshifted, x natural (8.5 MB)
__device__ float2 g_fimg[BN*DN*HK];     // image rffts, y fftshifted
__device__ float2 g_G1[NBTG*DN*WIN];    // stage-1 results (24.6 MB)
__device__ float  g_corr[NBTG];
__device__ int    g_argm[NBTG];

__device__ __forceinline__ float2 cmulf(float2 a, float2 b){
    return make_float2(a.x*b.x - a.y*b.y, a.x*b.y + a.y*b.x);
}

// per-block forward twiddle table: Ef[j] = exp(-2*pi*i*j/128)
__device__ __forceinline__ void make_tw(float2* Ef, int tid){
    if (tid < 128){
        float s, c;
        sincosf(-6.283185307179586f * (float)tid * (1.0f/128.0f), &s, &c);
        Ef[tid] = make_float2(c, s);
    }
}

// ---------------- warp-local 128-pt FFT: one warp, 2 butterflies/thread ------
__device__ __forceinline__ void fft128_w32(float2* col, const float2* Ef, int lane){
    for (int shift = 6; shift >= 0; shift--){
        int half = 1 << shift;
        int twsh = 6 - shift;               // Ef stride = 1 << twsh
        #pragma unroll
        for (int k = 0; k < 2; k++){
            int bf   = lane + k*32;         // 0..63
            int j    = bf & (half - 1);
            int grp  = bf >> shift;
            int base = (grp << (shift + 1)) + j;
            float2 u = col[base];
            float2 v = col[base + half];
            float2 d = make_float2(u.x - v.x, u.y - v.y);
            col[base]        = make_float2(u.x + v.x, u.y + v.y);
            col[base + half] = cmulf(d, Ef[j << twsh]);
        }
        __syncwarp();
    }
    float2 r[4];
    #pragma unroll
    for (int k = 0; k < 4; k++) r[k] = col[lane + k*32];
    __syncwarp();
    #pragma unroll
    for (int k = 0; k < 4; k++){
        int y = lane + k*32;
        col[(int)(__brev((unsigned)y) >> 25)] = r[k];
    }
    __syncwarp();
}

// ---------------- pass 1: row rffts (vol rows + img rows), warp-per-row ------
// blocks [0, 2048): volume rows; blocks [2048, 2112): image rows.
__global__ void __launch_bounds__(256) kPre(const float* __restrict__ vol,
                                            const float* __restrict__ imgs){
    __shared__ float2 ws[8][128];
    __shared__ float2 Ef[128];
    int tid = threadIdx.x, wid = tid >> 5, lane = tid & 31;
    make_tw(Ef, tid);
    __syncthreads();
    float2* w = ws[wid];
    if (blockIdx.x < 2048){
        int row = blockIdx.x * 8 + wid;       // 0..16383
        int z = row >> 7, y = row & 127;
        float fz = (float)(z - 64) * (1.0f/128.0f);
        float fy = (float)(y - 64) * (1.0f/128.0f);
        float fzy = fz*fz + fy*fy;
        #pragma unroll
        for (int k = 0; k < 4; k++){
            int x = lane + k*32;
            float fx = (float)(x - 64) * (1.0f/128.0f);
            float r  = sqrtf(fzy + fx*fx);
            float wt;
            if (r < 1e-12f) wt = 1.0f;
            else { float pr = 3.14159265358979f * r; wt = __sinf(pr) / pr; }
            wt = wt * wt;
            w[(x + 64) & 127] = make_float2(vol[(z*DN + y)*DN + x] * wt, 0.0f);
        }
        __syncwarp();
        fft128_w32(w, Ef, lane);
        #pragma unroll
        for (int k = 0; k < 3; k++){
            int x = lane + k*32;
            if (x < HK) g_vf[(z*DN + y)*HK + x] = w[x];
        }
    } else {
        int row = (blockIdx.x - 2048) * 8 + wid;  // 0..511
        int b = row >> 7, r = row & 127;
        #pragma unroll
        for (int k = 0; k < 4; k++){
            int x = lane + k*32;
            w[(x + 64) & 127] = make_float2(imgs[(b*DN + r)*DN + x], 0.0f);
        }
        __syncwarp();
        fft128_w32(w, Ef, lane);
        #pragma unroll
        for (int k = 0; k < 3; k++){
            int x = lane + k*32;
            if (x < HK) g_fimg[(b*DN + r)*HK + x] = w[x];
        }
    }
}

// ---------------- pass 2: y-FFT tiles (vol planes + image planes), in place --
// blocks [0, 1152): vol (z, kx-tile); blocks [1152, 1152+36): img (b, kx-tile).
__global__ void __launch_bounds__(256) kMid(){
    __shared__ float2 a[8][CP];
    __shared__ float2 Ef[128];
    int tid = threadIdx.x;
    make_tw(Ef, tid);
    float2* base;
    int kt;
    if (blockIdx.x < DN*KT){
        int z = blockIdx.x / KT;
        kt = blockIdx.x % KT;
        base = g_vf + z*DN*HK;
    } else {
        int u = blockIdx.x - DN*KT;
        int b = u / KT;
        kt = u % KT;
        base = g_fimg + b*DN*HK;
    }
    int kx0 = kt * 8;
    #pragma unroll
    for (int k = 0; k < 4; k++){
        int idx = tid + k*256;
        int y = idx >> 3, c = idx & 7;
        int kx = kx0 + c;
        if (kx < HK){
            int ys = (y + 64) & 127;
            a[c][y] = base[ys*HK + kx];
        }
    }
    __syncthreads();
    int wid = tid >> 5, lane = tid & 31;
    if (kx0 + wid < HK) fft128_w32(a[wid], Ef, lane);
    __syncthreads();
    #pragma unroll
    for (int k = 0; k < 4; k++){
        int idx = tid + k*256;
        int y = idx >> 3, c = idx & 7;
        int kx = kx0 + c;
        if (kx < HK){
            int ys = (y + 64) & 127;
            base[ys*HK + kx] = a[c][y];
        }
    }
}

// ---------------- pass 3: z-FFT tiles on volume, in place --------------------
__global__ void __launch_bounds__(256) kVolZT(){
    __shared__ float2 a[8][CP];
    __shared__ float2 Ef[128];
    int tid = threadIdx.x;
    int sy  = blockIdx.x / KT;
    int kt  = blockIdx.x % KT;
    int kx0 = kt * 8;
    make_tw(Ef, tid);
    #pragma unroll
    for (int k = 0; k < 4; k++){
        int idx = tid + k*256;
        int zz = idx >> 3, c = idx & 7;
        int kx = kx0 + c;
        if (kx < HK){
            int zs = (zz + 64) & 127;
            a[c][zz] = g_vf[(zs*DN + sy)*HK + kx];
        }
    }
    __syncthreads();
    int wid = tid >> 5, lane = tid & 31;
    if (kx0 + wid < HK) fft128_w32(a[wid], Ef, lane);
    __syncthreads();
    #pragma unroll
    for (int k = 0; k < 4; k++){
        int idx = tid + k*256;
        int zz = idx >> 3, c = idx & 7;
        int kx = kx0 + c;
        if (kx < HK){
            int zs = (zz + 64) & 127;
            g_vf[(zs*DN + sy)*HK + kx] = a[c][zz];
        }
    }
}

// ---------------- matcher stage A: slice extraction + column DFT -------------
// one block per (bid, stripe): grid = NBTG*4
__global__ void __launch_bounds__(256) kMatchA(const float* __restrict__ ctf,
                                               const float* __restrict__ rotm,
                                               const float* __restrict__ gridm){
    __shared__ float2 Pp[32][HK];     // product stripe (signs/alpha folded)
    __shared__ float2 Ei[128];        // exp(+2*pi*i*j/128)
    __shared__ float  Ac[3], Bc[3];

    int tid = threadIdx.x;
    int bid    = blockIdx.x >> 2;
    int stripe = blockIdx.x & 3;
    int b  = bid / PERB;
    int rr = bid % PERB;
    int t  = rr / GN;
    int g  = rr % GN;
    int hbase = stripe * 32;

    if (tid < 128){
        float s, c;
        sincosf(6.283185307179586f * (float)tid * (1.0f/128.0f), &s, &c);
        Ei[tid] = make_float2(c, s);
    }
    if (tid < 3){
        int i  = tid;
        int ii = 2 - i;
        const float* R  = rotm  + ((b*TN + t)*3 + ii)*3;
        const float* Gm = gridm + g*9;
        Ac[i] = R[0]*Gm[1] + R[1]*Gm[4] + R[2]*Gm[7];
        Bc[i] = R[0]*Gm[0] + R[1]*Gm[3] + R[2]*Gm[6];
    }
    __syncthreads();
    float A0=Ac[0], A1=Ac[1], A2=Ac[2], B0=Bc[0], B1=Bc[1], B2=Bc[2];

    const float*  ctfb = ctf    + b*DN*HK;
    const float2* fib  = g_fimg + b*DN*HK;

    // ---- stage 0: slice extraction + product ----
    for (int idx = tid; idx < 32*HK; idx += 256){
        int hh = idx / HK;
        int l  = idx - hh*HK;
        int h  = hbase + hh;
        float hm = (float)(h - 64);
        float lf = (float)l;
        float v0 = A0*hm + B0*lf;
        float v1 = A1*hm + B1*lf;
        float v2 = A2*hm + B2*lf;
        bool neg = (v2 < 0.0f);
        if (neg){ v0 = -v0; v1 = -v1; v2 = -v2; }
        float zc = v0 + 64.0f, yc = v1 + 64.0f, xc = v2;
        float zf = floorf(zc), yf = floorf(yc), xf = floorf(xc);
        int z0 = (int)zf, y0 = (int)yf, x0 = (int)xf;
        float fz = zc - zf, fy = yc - yf, fx = xc - xf;
        float2 acc = make_float2(0.0f, 0.0f);
        #pragma unroll
        for (int dz = 0; dz < 2; dz++){
            int zi = z0 + dz;
            if (zi < 0 || zi >= DN) continue;
            float wz = dz ? fz : 1.0f - fz;
            #pragma unroll
            for (int dy = 0; dy < 2; dy++){
                int yi = y0 + dy;
                if (yi < 0 || yi >= DN) continue;
                float wzy = wz * (dy ? fy : 1.0f - fy);
                #pragma unroll
                for (int dx = 0; dx < 2; dx++){
                    int xi = x0 + dx;
                    if (xi < 0 || xi >= HK) continue;
                    float ww = wzy * (dx ? fx : 1.0f - fx);
                    float2 vv = __ldg(&g_vf[(zi*DN + yi)*HK + xi]);
                    acc.x += vv.x * ww;
                    acc.y += vv.y * ww;
                }
            }
        }
        if (neg) acc.y = -acc.y;                 // conj
        float  cf = __ldg(&ctfb[h*HK + l]);
        float2 fi = fib[h*HK + l];
        float px = cf * (fi.x*acc.x + fi.y*acc.y);
        float py = cf * (fi.y*acc.x - fi.x*acc.y);
        float sgn = ((h + l) & 1) ? -1.0f : 1.0f;
        if (l != 0 && l != 64) sgn *= 2.0f;      // Hermitian alpha weight
        Pp[hh][l] = make_float2(px*sgn, py*sgn);
    }
    __syncthreads();

    // ---- stage 1: contract 65 x-freqs -> 24 output columns ----
    // thread (row1 = tid>>3, cg = tid&7) handles v = 3*cg + {0,1,2}
    {
        int row1 = tid >> 3;
        int cg   = tid & 7;
        int sb0  = H0 + 3*cg;
        float2 a0 = make_float2(0.f,0.f), a1 = a0, a2 = a0;
        int i0 = 0, i1 = 0, i2 = 0;
        for (int l = 0; l < HK; l++){
            float2 p  = Pp[row1][l];
            float2 w0 = Ei[i0];
            float2 w1 = Ei[i1];
            float2 w2 = Ei[i2];
            a0.x += p.x*w0.x - p.y*w0.y;  a0.y += p.x*w0.y + p.y*w0.x;
            a1.x += p.x*w1.x - p.y*w1.y;  a1.y += p.x*w1.y + p.y*w1.x;
            a2.x += p.x*w2.x - p.y*w2.y;  a2.y += p.x*w2.y + p.y*w2.x;
            i0 = (i0 + sb0    ) & 127;
            i1 = (i1 + sb0 + 1) & 127;
            i2 = (i2 + sb0 + 2) & 127;
        }
        float2* dst = g_G1 + (bid*DN + hbase + row1)*WIN + 3*cg;
        dst[0] = a0;
        dst[1] = a1;
        dst[2] = a2;
    }
}

// ---------------- matcher stage B: row DFT + windowed argmax -----------------
__global__ void __launch_bounds__(256) kMatchB(){
    __shared__ float2 G1s[DN*WIN];    // 24 KB
    __shared__ float2 Ei[128];
    __shared__ float  rv[256];
    __shared__ int    ri[256];
    int tid = threadIdx.x;
    int bid = blockIdx.x;

    if (tid < 128){
        float s, c;
        sincosf(6.283185307179586f * (float)tid * (1.0f/128.0f), &s, &c);
        Ei[tid] = make_float2(c, s);
    }
    const float2* src = g_G1 + bid*DN*WIN;
    for (int idx = tid; idx < DN*WIN; idx += 256) G1s[idx] = src[idx];
    __syncthreads();

    float best = -3.4e38f;
    int bestIdx = 0x7fffffff;
    if (tid < 192){
        int v  = tid % 24;
        int ug = tid / 24;
        int ub0 = H0 + 3*ug;
        float r0 = 0.f, r1 = 0.f, r2 = 0.f;
        int i0 = 0, i1 = 0, i2 = 0;
        for (int h = 0; h < 128; h++){
            float2 gv = G1s[h*WIN + v];
            float2 w0 = Ei[i0];
            float2 w1 = Ei[i1];
            float2 w2 = Ei[i2];
            r0 += gv.x*w0.x - gv.y*w0.y;
            r1 += gv.x*w1.x - gv.y*w1.y;
            r2 += gv.x*w2.x - gv.y*w2.y;
            i0 = (i0 + ub0    ) & 127;
            i1 = (i1 + ub0 + 1) & 127;
            i2 = (i2 + ub0 + 2) & 127;
        }
        #pragma unroll
        for (int j = 0; j < 3; j++){
            int u = 3*ug + j;
            float val = (j == 0 ? r0 : (j == 1 ? r1 : r2)) * (1.0f/16384.0f);
            if (u & 1) val = -val;                  // (-1)^(52+u)
            int idx = u*WIN + v;
            if (val > best || (val == best && idx < bestIdx)){ best = val; bestIdx = idx; }
        }
    }
    rv[tid] = best; ri[tid] = bestIdx;
    __syncthreads();
    for (int s = 128; s; s >>= 1){
        if (tid < s){
            float v2 = rv[tid+s]; int i2 = ri[tid+s];
            if (v2 > rv[tid] || (v2 == rv[tid] && i2 < ri[tid])){ rv[tid] = v2; ri[tid] = i2; }
        }
        __syncthreads();
    }
    if (tid == 0){ g_corr[bid] = rv[0]; g_argm[bid] = ri[0]; }
}

// ---------------- final per-batch reduction ----------------
__global__ void __launch_bounds__(256) kReduce(const float* __restrict__ gridm,
                                               float* __restrict__ out){
    __shared__ float sv[256];
    __shared__ int   si[256];
    __shared__ float s_mean, s_std;
    __shared__ float s_val[2];
    __shared__ int   s_idx[2];
    int b = blockIdx.x, tid = threadIdx.x;
    float v = (tid < PERB) ? g_corr[b*PERB + tid] : 0.0f;

    sv[tid] = (tid < PERB) ? v : 0.0f;
    __syncthreads();
    for (int s = 128; s; s >>= 1){ if (tid < s) sv[tid] += sv[tid+s]; __syncthreads(); }
    if (tid == 0) s_mean = sv[0] / (float)PERB;
    __syncthreads();
    float mean = s_mean;
    float d = (tid < PERB) ? (v - mean) : 0.0f;
    sv[tid] = d * d;
    __syncthreads();
    for (int s = 128; s; s >>= 1){ if (tid < s) sv[tid] += sv[tid+s]; __syncthreads(); }
    if (tid == 0) s_std = sqrtf(sv[0] / (float)(PERB - 1));
    __syncthreads();
    float stdv = s_std;

    for (int k = 0; k < 2; k++){
        bool excl = (k == 1 && tid == s_idx[0]);
        sv[tid] = (tid < PERB && !excl) ? v : -3.4e38f;
        si[tid] = tid;
        __syncthreads();
        for (int s = 128; s; s >>= 1){
            if (tid < s){
                float v2 = sv[tid+s]; int i2 = si[tid+s];
                if (v2 > sv[tid] || (v2 == sv[tid] && i2 < si[tid])){ sv[tid] = v2; si[tid] = i2; }
            }
            __syncthreads();
        }
        if (tid == 0){ s_val[k] = sv[0]; s_idx[k] = si[0]; }
        __syncthreads();
    }

    if (tid < 2){
        int k = tid;
        float val = s_val[k];
        int   idx = s_idx[k];
        int   gg  = idx % GN;
        int   a   = g_argm[b*PERB + idx];
        int   u   = a / WIN;
        int   vv  = a - u*WIN;
        int slot  = b*2 + k;
        out[slot] = val;
        for (int j = 0; j < 9; j++) out[8 + slot*9 + j] = gridm[gg*9 + j];
        out[80 + slot*2 + 0] = -((float)(H0 + vv) - 64.0f) * 1.5f;
        out[80 + slot*2 + 1] = -((float)(H0 + u)  - 64.0f) * 1.5f;
        float zz = (val - mean) / (stdv * 1.41421356237f);
        out[96 + slot] = 0.5f * (1.0f + erff(zz));
    }
}

// ---------------- launch ----------------
extern "C" void kernel_launch(void* const* d_in, const int* in_sizes, int n_in,
                              void* d_out, int out_size){
    const float* vol   = (const float*)d_in[0];
    const float* imgs  = (const float*)d_in[1];
    const float* ctf   = (const float*)d_in[2];
    const float* rotm  = (const float*)d_in[3];
    const float* gridm = (const float*)d_in[4];

    kPre<<<2112, 256>>>(vol, imgs);              // launch 1: vol-X + img rows
    kMid<<<DN*KT + BN*KT, 256>>>();              // launch 2: vol-Y + img cols
    kVolZT<<<DN*KT, 256>>>();                    // launch 3: vol-Z
    kMatchA<<<NBTG*4, 256>>>(ctf, rotm, gridm);  // launch 4  <- profiled
    kMatchB<<<NBTG, 256>>>();                    // launch 5
    kReduce<<<BN, 256>>>(gridm, (float*)d_out);  // launch 6
}

// round 8
// speedup vs baseline: 1.3545x; 1.0435x over previous
#include <cuda_runtime.h>
#include <math.h>

#define DN   128
#define HK   65
#define BN   4
#define TN   2
#define GN   125
#define PERB (TN*GN)      // 250
#define NBTG (BN*PERB)    // 1000
#define WIN  24
#define H0   52
#define KT   9            // ceil(65/8) kx tiles
#define CP   130          // padded column stride for tile kernels

// ---------------- scratch (static device memory; no allocation) ----------------
__device__ float2 g_vf[DN*DN*HK];       // vol rfft, z/y fftshifted, x natural (8.5 MB)
__device__ float2 g_fimg[BN*DN*HK];     // image rffts, y fftshifted
__device__ float2 g_G1[NBTG*DN*WIN];    // stage-1 results (24.6 MB)
__device__ float  g_corr[NBTG];
__device__ int    g_argm[NBTG];

__device__ __forceinline__ float2 cmulf(float2 a, float2 b){
    return make_float2(a.x*b.x - a.y*b.y, a.x*b.y + a.y*b.x);
}

// per-block forward twiddle table: Ef[j] = exp(-2*pi*i*j/128)
__device__ __forceinline__ void make_tw(float2* Ef, int tid){
    if (tid < 128){
        float s, c;
        sincosf(-6.283185307179586f * (float)tid * (1.0f/128.0f), &s, &c);
        Ef[tid] = make_float2(c, s);
    }
}

// ---------------- warp-local 128-pt FFT: one warp, 2 butterflies/thread ------
__device__ __forceinline__ void fft128_w32(float2* col, const float2* Ef, int lane){
    for (int shift = 6; shift >= 0; shift--){
        int half = 1 << shift;
        int twsh = 6 - shift;               // Ef stride = 1 << twsh
        #pragma unroll
        for (int k = 0; k < 2; k++){
            int bf   = lane + k*32;         // 0..63
            int j    = bf & (half - 1);
            int grp  = bf >> shift;
            int base = (grp << (shift + 1)) + j;
            float2 u = col[base];
            float2 v = col[base + half];
            float2 d = make_float2(u.x - v.x, u.y - v.y);
            col[base]        = make_float2(u.x + v.x, u.y + v.y);
            col[base + half] = cmulf(d, Ef[j << twsh]);
        }
        __syncwarp();
    }
    float2 r[4];
    #pragma unroll
    for (int k = 0; k < 4; k++) r[k] = col[lane + k*32];
    __syncwarp();
    #pragma unroll
    for (int k = 0; k < 4; k++){
        int y = lane + k*32;
        col[(int)(__brev((unsigned)y) >> 25)] = r[k];
    }
    __syncwarp();
}

// ---------------- pass 1: row rffts (vol rows + img rows), warp-per-row ------
__global__ void __launch_bounds__(256) kPre(const float* __restrict__ vol,
                                            const float* __restrict__ imgs){
    __shared__ float2 ws[8][128];
    __shared__ float2 Ef[128];
    int tid = threadIdx.x, wid = tid >> 5, lane = tid & 31;
    make_tw(Ef, tid);
    __syncthreads();
    float2* w = ws[wid];
    if (blockIdx.x < 2048){
        int row = blockIdx.x * 8 + wid;       // 0..16383
        int z = row >> 7, y = row & 127;
        float fz = (float)(z - 64) * (1.0f/128.0f);
        float fy = (float)(y - 64) * (1.0f/128.0f);
        float fzy = fz*fz + fy*fy;
        #pragma unroll
        for (int k = 0; k < 4; k++){
            int x = lane + k*32;
            float fx = (float)(x - 64) * (1.0f/128.0f);
            float r  = sqrtf(fzy + fx*fx);
            float wt;
            if (r < 1e-12f) wt = 1.0f;
            else { float pr = 3.14159265358979f * r; wt = __sinf(pr) / pr; }
            wt = wt * wt;
            w[(x + 64) & 127] = make_float2(vol[(z*DN + y)*DN + x] * wt, 0.0f);
        }
        __syncwarp();
        fft128_w32(w, Ef, lane);
        #pragma unroll
        for (int k = 0; k < 3; k++){
            int x = lane + k*32;
            if (x < HK) g_vf[(z*DN + y)*HK + x] = w[x];
        }
    } else {
        int row = (blockIdx.x - 2048) * 8 + wid;  // 0..511
        int b = row >> 7, r = row & 127;
        #pragma unroll
        for (int k = 0; k < 4; k++){
            int x = lane + k*32;
            w[(x + 64) & 127] = make_float2(imgs[(b*DN + r)*DN + x], 0.0f);
        }
        __syncwarp();
        fft128_w32(w, Ef, lane);
        #pragma unroll
        for (int k = 0; k < 3; k++){
            int x = lane + k*32;
            if (x < HK) g_fimg[(b*DN + r)*HK + x] = w[x];
        }
    }
}

// ---------------- pass 2: y-FFT tiles (vol planes + image planes), in place --
__global__ void __launch_bounds__(256) kMid(){
    __shared__ float2 a[8][CP];
    __shared__ float2 Ef[128];
    int tid = threadIdx.x;
    make_tw(Ef, tid);
    float2* base;
    int kt;
    if (blockIdx.x < DN*KT){
        int z = blockIdx.x / KT;
        kt = blockIdx.x % KT;
        base = g_vf + z*DN*HK;
    } else {
        int u = blockIdx.x - DN*KT;
        int b = u / KT;
        kt = u % KT;
        base = g_fimg + b*DN*HK;
    }
    int kx0 = kt * 8;
    #pragma unroll
    for (int k = 0; k < 4; k++){
        int idx = tid + k*256;
        int y = idx >> 3, c = idx & 7;
        int kx = kx0 + c;
        if (kx < HK){
            int ys = (y + 64) & 127;
            a[c][y] = base[ys*HK + kx];
        }
    }
    __syncthreads();
    int wid = tid >> 5, lane = tid & 31;
    if (kx0 + wid < HK) fft128_w32(a[wid], Ef, lane);
    __syncthreads();
    #pragma unroll
    for (int k = 0; k < 4; k++){
        int idx = tid + k*256;
        int y = idx >> 3, c = idx & 7;
        int kx = kx0 + c;
        if (kx < HK){
            int ys = (y + 64) & 127;
            base[ys*HK + kx] = a[c][y];
        }
    }
}

// ---------------- pass 3: z-FFT tiles on volume, in place --------------------
__global__ void __launch_bounds__(256) kVolZT(){
    __shared__ float2 a[8][CP];
    __shared__ float2 Ef[128];
    int tid = threadIdx.x;
    int sy  = blockIdx.x / KT;
    int kt  = blockIdx.x % KT;
    int kx0 = kt * 8;
    make_tw(Ef, tid);
    #pragma unroll
    for (int k = 0; k < 4; k++){
        int idx = tid + k*256;
        int zz = idx >> 3, c = idx & 7;
        int kx = kx0 + c;
        if (kx < HK){
            int zs = (zz + 64) & 127;
            a[c][zz] = g_vf[(zs*DN + sy)*HK + kx];
        }
    }
    __syncthreads();
    int wid = tid >> 5, lane = tid & 31;
    if (kx0 + wid < HK) fft128_w32(a[wid], Ef, lane);
    __syncthreads();
    #pragma unroll
    for (int k = 0; k < 4; k++){
        int idx = tid + k*256;
        int zz = idx >> 3, c = idx & 7;
        int kx = kx0 + c;
        if (kx < HK){
            int zs = (zz + 64) & 127;
            g_vf[(zs*DN + sy)*HK + kx] = a[c][zz];
        }
    }
}

// ---------------- matcher stage A: slice extraction + column DFT -------------
// one block per (bid, stripe): grid = NBTG*4
__global__ void __launch_bounds__(256) kMatchA(const float* __restrict__ ctf,
                                               const float* __restrict__ rotm,
                                               const float* __restrict__ gridm){
    __shared__ float2 Pp[32][HK];     // product stripe (signs/alpha folded)
    __shared__ float2 Ei[128];        // exp(+2*pi*i*j/128)
    __shared__ float  Ac[3], Bc[3];

    int tid = threadIdx.x;
    int bid    = blockIdx.x >> 2;
    int stripe = blockIdx.x & 3;
    int b  = bid / PERB;
    int rr = bid % PERB;
    int t  = rr / GN;
    int g  = rr % GN;
    int hbase = stripe * 32;

    if (tid < 128){
        float s, c;
        sincosf(6.283185307179586f * (float)tid * (1.0f/128.0f), &s, &c);
        Ei[tid] = make_float2(c, s);
    }
    if (tid < 3){
        int i  = tid;
        int ii = 2 - i;
        const float* R  = rotm  + ((b*TN + t)*3 + ii)*3;
        const float* Gm = gridm + g*9;
        Ac[i] = R[0]*Gm[1] + R[1]*Gm[4] + R[2]*Gm[7];
        Bc[i] = R[0]*Gm[0] + R[1]*Gm[3] + R[2]*Gm[6];
    }
    __syncthreads();
    float A0=Ac[0], A1=Ac[1], A2=Ac[2], B0=Bc[0], B1=Bc[1], B2=Bc[2];

    const float*  ctfb = ctf    + b*DN*HK;
    const float2* fib  = g_fimg + b*DN*HK;

    // ---- stage 0: slice extraction + product ----
    for (int idx = tid; idx < 32*HK; idx += 256){
        int hh = idx / HK;
        int l  = idx - hh*HK;
        int h  = hbase + hh;
        float hm = (float)(h - 64);
        float lf = (float)l;
        float v0 = A0*hm + B0*lf;
        float v1 = A1*hm + B1*lf;
        float v2 = A2*hm + B2*lf;
        bool neg = (v2 < 0.0f);
        if (neg){ v0 = -v0; v1 = -v1; v2 = -v2; }
        float zc = v0 + 64.0f, yc = v1 + 64.0f, xc = v2;
        float zf = floorf(zc), yf = floorf(yc), xf = floorf(xc);
        int z0 = (int)zf, y0 = (int)yf, x0 = (int)xf;
        float fz = zc - zf, fy = yc - yf, fx = xc - xf;
        float2 acc = make_float2(0.0f, 0.0f);
        #pragma unroll
        for (int dz = 0; dz < 2; dz++){
            int zi = z0 + dz;
            if (zi < 0 || zi >= DN) continue;
            float wz = dz ? fz : 1.0f - fz;
            #pragma unroll
            for (int dy = 0; dy < 2; dy++){
                int yi = y0 + dy;
                if (yi < 0 || yi >= DN) continue;
                float wzy = wz * (dy ? fy : 1.0f - fy);
                #pragma unroll
                for (int dx = 0; dx < 2; dx++){
                    int xi = x0 + dx;
                    if (xi < 0 || xi >= HK) continue;
                    float ww = wzy * (dx ? fx : 1.0f - fx);
                    float2 vv = __ldg(&g_vf[(zi*DN + yi)*HK + xi]);
                    acc.x += vv.x * ww;
                    acc.y += vv.y * ww;
                }
            }
        }
        if (neg) acc.y = -acc.y;                 // conj
        float  cf = __ldg(&ctfb[h*HK + l]);
        float2 fi = fib[h*HK + l];
        float px = cf * (fi.x*acc.x + fi.y*acc.y);
        float py = cf * (fi.y*acc.x - fi.x*acc.y);
        float sgn = ((h + l) & 1) ? -1.0f : 1.0f;
        if (l != 0 && l != 64) sgn *= 2.0f;      // Hermitian alpha weight
        Pp[hh][l] = make_float2(px*sgn, py*sgn);
    }
    __syncthreads();

    // ---- stage 1: contract 65 x-freqs -> 24 output columns ----
    // thread (row1 = tid>>3, cg = tid&7) handles v = 3*cg + {0,1,2}.
    // Twiddles via register recurrence (1 LDS/iter instead of 4).
    {
        int row1 = tid >> 3;
        int cg   = tid & 7;
        int sb0  = H0 + 3*cg;
        float2 s0 = Ei[sb0];
        float2 s1 = Ei[sb0 + 1];
        float2 s2 = Ei[sb0 + 2];
        float2 w0 = make_float2(1.f, 0.f), w1 = w0, w2 = w0;
        float2 a0 = make_float2(0.f, 0.f), a1 = a0, a2 = a0;
        for (int l = 0; l < HK; l++){
            float2 p = Pp[row1][l];
            a0.x += p.x*w0.x - p.y*w0.y;  a0.y += p.x*w0.y + p.y*w0.x;
            a1.x += p.x*w1.x - p.y*w1.y;  a1.y += p.x*w1.y + p.y*w1.x;
            a2.x += p.x*w2.x - p.y*w2.y;  a2.y += p.x*w2.y + p.y*w2.x;
            float t0 = w0.x*s0.x - w0.y*s0.y;  w0.y = w0.x*s0.y + w0.y*s0.x;  w0.x = t0;
            float t1 = w1.x*s1.x - w1.y*s1.y;  w1.y = w1.x*s1.y + w1.y*s1.x;  w1.x = t1;
            float t2 = w2.x*s2.x - w2.y*s2.y;  w2.y = w2.x*s2.y + w2.y*s2.x;  w2.x = t2;
        }
        float2* dst = g_G1 + (bid*DN + hbase + row1)*WIN + 3*cg;
        dst[0] = a0;
        dst[1] = a1;
        dst[2] = a2;
    }
}

// ---------------- matcher stage B: row DFT + windowed argmax -----------------
__global__ void __launch_bounds__(256) kMatchB(){
    __shared__ float2 G1s[DN*WIN];    // 24 KB
    __shared__ float2 Ei[128];
    __shared__ float  rv[256];
    __shared__ int    ri[256];
    int tid = threadIdx.x;
    int bid = blockIdx.x;

    if (tid < 128){
        float s, c;
        sincosf(6.283185307179586f * (float)tid * (1.0f/128.0f), &s, &c);
        Ei[tid] = make_float2(c, s);
    }
    const float2* src = g_G1 + bid*DN*WIN;
    for (int idx = tid; idx < DN*WIN; idx += 256) G1s[idx] = src[idx];
    __syncthreads();

    float best = -3.4e38f;
    int bestIdx = 0x7fffffff;
    if (tid < 192){
        int v  = tid % 24;
        int ug = tid / 24;
        int ub0 = H0 + 3*ug;
        float2 s0 = Ei[ub0];
        float2 s1 = Ei[ub0 + 1];
        float2 s2 = Ei[ub0 + 2];
        float2 w0 = make_float2(1.f, 0.f), w1 = w0, w2 = w0;
        float r0 = 0.f, r1 = 0.f, r2 = 0.f;
        for (int h = 0; h < 128; h++){
            float2 gv = G1s[h*WIN + v];
            r0 += gv.x*w0.x - gv.y*w0.y;
            r1 += gv.x*w1.x - gv.y*w1.y;
            r2 += gv.x*w2.x - gv.y*w2.y;
            float t0 = w0.x*s0.x - w0.y*s0.y;  w0.y = w0.x*s0.y + w0.y*s0.x;  w0.x = t0;
            float t1 = w1.x*s1.x - w1.y*s1.y;  w1.y = w1.x*s1.y + w1.y*s1.x;  w1.x = t1;
            float t2 = w2.x*s2.x - w2.y*s2.y;  w2.y = w2.x*s2.y + w2.y*s2.x;  w2.x = t2;
        }
        #pragma unroll
        for (int j = 0; j < 3; j++){
            int u = 3*ug + j;
            float val = (j == 0 ? r0 : (j == 1 ? r1 : r2)) * (1.0f/16384.0f);
            if (u & 1) val = -val;                  // (-1)^(52+u)
            int idx = u*WIN + v;
            if (val > best || (val == best && idx < bestIdx)){ best = val; bestIdx = idx; }
        }
    }
    rv[tid] = best; ri[tid] = bestIdx;
    __syncthreads();
    for (int s = 128; s; s >>= 1){
        if (tid < s){
            float v2 = rv[tid+s]; int i2 = ri[tid+s];
            if (v2 > rv[tid] || (v2 == rv[tid] && i2 < ri[tid])){ rv[tid] = v2; ri[tid] = i2; }
        }
        __syncthreads();
    }
    if (tid == 0){ g_corr[bid] = rv[0]; g_argm[bid] = ri[0]; }
}

// ---------------- final per-batch reduction ----------------
__global__ void __launch_bounds__(256) kReduce(const float* __restrict__ gridm,
                                               float* __restrict__ out){
    __shared__ float sv[256];
    __shared__ int   si[256];
    __shared__ float s_mean, s_std;
    __shared__ float s_val[2];
    __shared__ int   s_idx[2];
    int b = blockIdx.x, tid = threadIdx.x;
    float v = (tid < PERB) ? g_corr[b*PERB + tid] : 0.0f;

    sv[tid] = (tid < PERB) ? v : 0.0f;
    __syncthreads();
    for (int s = 128; s; s >>= 1){ if (tid < s) sv[tid] += sv[tid+s]; __syncthreads(); }
    if (tid == 0) s_mean = sv[0] / (float)PERB;
    __syncthreads();
    float mean = s_mean;
    float d = (tid < PERB) ? (v - mean) : 0.0f;
    sv[tid] = d * d;
    __syncthreads();
    for (int s = 128; s; s >>= 1){ if (tid < s) sv[tid] += sv[tid+s]; __syncthreads(); }
    if (tid == 0) s_std = sqrtf(sv[0] / (float)(PERB - 1));
    __syncthreads();
    float stdv = s_std;

    for (int k = 0; k < 2; k++){
        bool excl = (k == 1 && tid == s_idx[0]);
        sv[tid] = (tid < PERB && !excl) ? v : -3.4e38f;
        si[tid] = tid;
        __syncthreads();
        for (int s = 128; s; s >>= 1){
            if (tid < s){
                float v2 = sv[tid+s]; int i2 = si[tid+s];
                if (v2 > sv[tid] || (v2 == sv[tid] && i2 < si[tid])){ sv[tid] = v2; si[tid] = i2; }
            }
            __syncthreads();
        }
        if (tid == 0){ s_val[k] = sv[0]; s_idx[k] = si[0]; }
        __syncthreads();
    }

    if (tid < 2){
        int k = tid;
        float val = s_val[k];
        int   idx = s_idx[k];
        int   gg  = idx % GN;
        int   a   = g_argm[b*PERB + idx];
        int   u   = a / WIN;
        int   vv  = a - u*WIN;
        int slot  = b*2 + k;
        out[slot] = val;
        for (int j = 0; j < 9; j++) out[8 + slot*9 + j] = gridm[gg*9 + j];
        out[80 + slot*2 + 0] = -((float)(H0 + vv) - 64.0f) * 1.5f;
        out[80 + slot*2 + 1] = -((float)(H0 + u)  - 64.0f) * 1.5f;
        float zz = (val - mean) / (stdv * 1.41421356237f);
        out[96 + slot] = 0.5f * (1.0f + erff(zz));
    }
}

// ---------------- launch ----------------
extern "C" void kernel_launch(void* const* d_in, const int* in_sizes, int n_in,
                              void* d_out, int out_size){
    const float* vol   = (const float*)d_in[0];
    const float* imgs  = (const float*)d_in[1];
    const float* ctf   = (const float*)d_in[2];
    const float* rotm  = (const float*)d_in[3];
    const float* gridm = (const float*)d_in[4];

    kPre<<<2112, 256>>>(vol, imgs);              // launch 1: vol-X + img rows
    kMid<<<DN*KT + BN*KT, 256>>>();              // launch 2: vol-Y + img cols
    kVolZT<<<DN*KT, 256>>>();                    // launch 3: vol-Z
    kMatchA<<<NBTG*4, 256>>>(ctf, rotm, gridm);  // launch 4  <- profiled
    kMatchB<<<NBTG, 256>>>();                    // launch 5
    kReduce<<<BN, 256>>>(gridm, (float*)d_out);  // launch 6
}